// round 1
// baseline (speedup 1.0000x reference)
#include <cuda_runtime.h>

#define BSZ 4096
#define TSZ 4096

// per-element loss partials (double for a safe deterministic reduction)
__device__ double g_loss_partial[BSZ];

__device__ __forceinline__ float ex2f(float x) {
    float y; asm("ex2.approx.f32 %0, %1;" : "=f"(y) : "f"(x)); return y;
}
__device__ __forceinline__ float rcpf(float x) {
    float y; asm("rcp.approx.f32 %0, %1;" : "=f"(y) : "f"(x)); return y;
}
// sigmoid with pre-scaled argument a' = -log2(e)*a  ->  1/(1+2^{a'})
__device__ __forceinline__ float sig_pre(float ap) { return rcpf(1.0f + ex2f(ap)); }
// tanh with pre-scaled argument p' = 2*log2(e)*p  ->  1 - 2/(1+2^{p'})
__device__ __forceinline__ float tanh_pre(float pp) { return fmaf(-2.0f, rcpf(1.0f + ex2f(pp)), 1.0f); }

// One thread per batch element. Encoder (T steps, keep-mask) then decoder
// (T steps autoregressive), writing masked `output` and accumulating the
// per-element loss partial.
__global__ void __launch_bounds__(32, 1) gru_kernel(
    const float* __restrict__ x, const int* __restrict__ lens,
    const float* __restrict__ eWih, const float* __restrict__ eWhh,
    const float* __restrict__ ebih, const float* __restrict__ ebhh,
    const float* __restrict__ dWih, const float* __restrict__ dWhh,
    const float* __restrict__ dbih, const float* __restrict__ dbhh,
    const float* __restrict__ linW, const float* __restrict__ linb,
    float* __restrict__ out_output)
{
    const int b   = blockIdx.x * 32 + threadIdx.x;
    const int len = lens[b];
    const float L2E  = 1.4426950408889634f;   // log2(e)
    const float NL2E = -L2E;
    const float P2L2E = 2.0f * L2E;

    const float* __restrict__ xrow = x + (long)b * TSZ;

    // ---------------- encoder weights (pre-scaled) ----------------
    // rows 0..5 of [r;z;n] stacking are r,z gates -> scale by -log2e
    float wi[6], wh[6][3], bs[6];
#pragma unroll
    for (int j = 0; j < 6; j++) {
        wi[j] = NL2E * eWih[j];
        bs[j] = NL2E * (ebih[j] + ebhh[j]);
#pragma unroll
        for (int k = 0; k < 3; k++) wh[j][k] = NL2E * eWhh[j * 3 + k];
    }
    // n-gate rows (6..8): keep i_n and h_n separate, scale both by 2*log2e
    float win[3], bin_[3], whn[3][3], bhn[3];
#pragma unroll
    for (int j = 0; j < 3; j++) {
        win[j]  = P2L2E * eWih[6 + j];
        bin_[j] = P2L2E * ebih[6 + j];
        bhn[j]  = P2L2E * ebhh[6 + j];
#pragma unroll
        for (int k = 0; k < 3; k++) whn[j][k] = P2L2E * eWhh[(6 + j) * 3 + k];
    }

    float h0 = 0.f, h1 = 0.f, h2 = 0.f;

    // ---------------- encoder loop ----------------
    for (int t = 0; t < TSZ; t++) {
        float xv = xrow[t];
        float a[6];
#pragma unroll
        for (int j = 0; j < 6; j++)
            a[j] = fmaf(h2, wh[j][2], fmaf(h1, wh[j][1], fmaf(h0, wh[j][0], fmaf(xv, wi[j], bs[j]))));
        float r0 = sig_pre(a[0]), r1 = sig_pre(a[1]), r2 = sig_pre(a[2]);
        float z0 = sig_pre(a[3]), z1 = sig_pre(a[4]), z2 = sig_pre(a[5]);

        float n_[3];
#pragma unroll
        for (int j = 0; j < 3; j++) {
            float inj = fmaf(xv, win[j], bin_[j]);
            float hnj = fmaf(h2, whn[j][2], fmaf(h1, whn[j][1], fmaf(h0, whn[j][0], bhn[j])));
            float rj = (j == 0) ? r0 : ((j == 1) ? r1 : r2);
            n_[j] = tanh_pre(fmaf(rj, hnj, inj));
        }
        float nh0 = fmaf(z0, h0 - n_[0], n_[0]);
        float nh1 = fmaf(z1, h1 - n_[1], n_[1]);
        float nh2 = fmaf(z2, h2 - n_[2], n_[2]);
        bool act = t < len;
        h0 = act ? nh0 : h0;
        h1 = act ? nh1 : h1;
        h2 = act ? nh2 : h2;
    }

    // features = sigmoid(h_final)
    h0 = sig_pre(NL2E * h0);
    h1 = sig_pre(NL2E * h1);
    h2 = sig_pre(NL2E * h2);

    // ---------------- decoder weights (pre-scaled) ----------------
    float vwi[6], vwh[6][3], vbs[6];
#pragma unroll
    for (int j = 0; j < 6; j++) {
        vwi[j] = NL2E * dWih[j];
        vbs[j] = NL2E * (dbih[j] + dbhh[j]);
#pragma unroll
        for (int k = 0; k < 3; k++) vwh[j][k] = NL2E * dWhh[j * 3 + k];
    }
    float vwin[3], vbin[3], vwhn[3][3], vbhn[3];
#pragma unroll
    for (int j = 0; j < 3; j++) {
        vwin[j] = P2L2E * dWih[6 + j];
        vbin[j] = P2L2E * dbih[6 + j];
        vbhn[j] = P2L2E * dbhh[6 + j];
#pragma unroll
        for (int k = 0; k < 3; k++) vwhn[j][k] = P2L2E * dWhh[(6 + j) * 3 + k];
    }
    const float lw0 = linW[0], lw1 = linW[1], lw2 = linW[2], lb = linb[0];

    float* __restrict__ orow = out_output + (long)b * TSZ;
    float inp = 0.f;
    double acc = 0.0;

    // ---------------- decoder loop ----------------
    for (int t = 0; t < TSZ; t++) {
        float a[6];
#pragma unroll
        for (int j = 0; j < 6; j++)
            a[j] = fmaf(h2, vwh[j][2], fmaf(h1, vwh[j][1], fmaf(h0, vwh[j][0], fmaf(inp, vwi[j], vbs[j]))));
        float r0 = sig_pre(a[0]), r1 = sig_pre(a[1]), r2 = sig_pre(a[2]);
        float z0 = sig_pre(a[3]), z1 = sig_pre(a[4]), z2 = sig_pre(a[5]);

        float n_[3];
#pragma unroll
        for (int j = 0; j < 3; j++) {
            float inj = fmaf(inp, vwin[j], vbin[j]);
            float hnj = fmaf(h2, vwhn[j][2], fmaf(h1, vwhn[j][1], fmaf(h0, vwhn[j][0], vbhn[j])));
            float rj = (j == 0) ? r0 : ((j == 1) ? r1 : r2);
            n_[j] = tanh_pre(fmaf(rj, hnj, inj));
        }
        h0 = fmaf(z0, h0 - n_[0], n_[0]);
        h1 = fmaf(z1, h1 - n_[1], n_[1]);
        h2 = fmaf(z2, h2 - n_[2], n_[2]);

        float outv = fmaf(h2, lw2, fmaf(h1, lw1, fmaf(h0, lw0, lb)));
        inp = outv;

        bool valid = t < len;
        float o  = valid ? outv : 0.f;
        orow[t] = o;
        float xv = xrow[t];
        float xm = valid ? xv : 0.f;
        float d  = xm - o;
        acc = fma((double)d, (double)d, acc);
    }

    g_loss_partial[b] = acc;
}

// Coalesced elementwise x_pad (zero past each sequence length)
__global__ void xpad_kernel(const float* __restrict__ x, const int* __restrict__ lens,
                            float* __restrict__ xpad)
{
    int idx = blockIdx.x * blockDim.x + threadIdx.x;   // exactly B*T threads
    int t = idx & (TSZ - 1);
    int b = idx >> 12;                                 // T = 4096 = 2^12
    float v = x[idx];
    xpad[idx] = (t < lens[b]) ? v : 0.f;
}

// Deterministic fixed-order reduction of the 4096 partials -> scalar loss
__global__ void loss_kernel(float* __restrict__ out_loss)
{
    __shared__ double s[1024];
    int tid = threadIdx.x;
    double a = 0.0;
    for (int i = tid; i < BSZ; i += 1024) a += g_loss_partial[i];
    s[tid] = a;
    __syncthreads();
    for (int off = 512; off > 0; off >>= 1) {
        if (tid < off) s[tid] += s[tid + off];
        __syncthreads();
    }
    if (tid == 0) out_loss[0] = (float)(s[0] / ((double)BSZ * (double)TSZ));
}

extern "C" void kernel_launch(void* const* d_in, const int* in_sizes, int n_in,
                              void* d_out, int out_size)
{
    const float* x    = (const float*)d_in[0];
    const int*   lens = (const int*)  d_in[1];
    const float* eWih = (const float*)d_in[2];
    const float* eWhh = (const float*)d_in[3];
    const float* ebih = (const float*)d_in[4];
    const float* ebhh = (const float*)d_in[5];
    const float* dWih = (const float*)d_in[6];
    const float* dWhh = (const float*)d_in[7];
    const float* dbih = (const float*)d_in[8];
    const float* dbhh = (const float*)d_in[9];
    const float* linW = (const float*)d_in[10];
    const float* linb = (const float*)d_in[11];

    float* out    = (float*)d_out;
    float* loss   = out;                       // [1]
    float* xpad   = out + 1;                   // [B*T]
    float* output = out + 1 + (long)BSZ * TSZ; // [B*T]

    gru_kernel<<<BSZ / 32, 32>>>(x, lens, eWih, eWhh, ebih, ebhh,
                                 dWih, dWhh, dbih, dbhh, linW, linb, output);
    xpad_kernel<<<(BSZ * TSZ) / 256, 256>>>(x, lens, xpad);
    loss_kernel<<<1, 1024>>>(loss);
}